// round 10
// baseline (speedup 1.0000x reference)
#include <cuda_runtime.h>
#include <cuda_bf16.h>
#include <math.h>

// inputs: x[f32] (unused), src[i32 E], dst[i32 E], path_len[i32 E], b[f32 5].
// output: f32 N*N.  out = zeros; out[src[i],dst[i]] = b[min(plen[i],5)-1],
// LAST duplicate (highest i) wins.
//
// Multisplit row-binning, no global atomics:
//   H2 : per-CTA smem histogram of src -> g_cnt[row][cta]   (transposed!)
//   RT : warp-per-row coalesced totals -> g_total
//   SC : exclusive scan of totals -> g_rowStart
//   OF : warp-per-row coalesced exclusive scan across ctas -> absolute offsets
//   B2 : per-CTA smem cursors; slot = smem atomicAdd -> g_bins[slot]={key,dst}
//   AP : one CTA per row: smem atomicMax(tile[dst], key) (key monotone in i),
//        then dense coalesced row store.

#ifndef MAX_PATH_DISTANCE
#define MAX_PATH_DISTANCE 5
#endif

#define N_MAX 8192
#define E_MAX (4 * 1024 * 1024)
#define NCTA  256

__device__ int  g_cnt[N_MAX * NCTA];   // [row][cta], 8 MB
__device__ int  g_total[N_MAX];
__device__ int  g_rowStart[N_MAX];
__device__ int2 g_bins[E_MAX];         // 32 MB

// ---------------- H2: per-CTA smem histogram ----------------
__global__ void hist2_kernel(const int* __restrict__ src, int n_pairs, int chunk) {
    __shared__ int cnt[N_MAX];
    int t = threadIdx.x, nt = blockDim.x, c = blockIdx.x;
    for (int i = t; i < N_MAX; i += nt) cnt[i] = 0;
    __syncthreads();

    int begin = c * chunk;                       // chunk is a multiple of 4
    int end = min(begin + chunk, n_pairs);
    int nfull = begin + ((end - begin) & ~3);

    for (int base = begin + t * 4; base < nfull; base += nt * 4) {
        int4 s = *reinterpret_cast<const int4*>(src + base);
        atomicAdd(&cnt[s.x], 1); atomicAdd(&cnt[s.y], 1);
        atomicAdd(&cnt[s.z], 1); atomicAdd(&cnt[s.w], 1);
    }
    for (int k = nfull + t; k < end; k += nt) atomicAdd(&cnt[src[k]], 1);
    __syncthreads();

    for (int i = t; i < N_MAX; i += nt)
        g_cnt[i * NCTA + c] = cnt[i];            // scattered, L2-merged
}

// ---------------- RT: warp-per-row totals (coalesced) ----------------
__global__ void rowtotal_kernel() {
    int wid  = threadIdx.x >> 5;
    int lane = threadIdx.x & 31;
    int r = blockIdx.x * (blockDim.x >> 5) + wid;
    if (r >= N_MAX) return;

    const int4* p = reinterpret_cast<const int4*>(&g_cnt[r * NCTA + lane * 8]);
    int4 a = p[0], bb = p[1];
    int s = a.x + a.y + a.z + a.w + bb.x + bb.y + bb.z + bb.w;
#pragma unroll
    for (int off = 16; off > 0; off >>= 1)
        s += __shfl_xor_sync(0xffffffffu, s, off);
    if (lane == 0) g_total[r] = s;
}

// ---------------- SC: exclusive scan of totals ----------------
__global__ void scan_kernel(int n) {
    __shared__ int sdata[1024];
    int t = threadIdx.x;
    int vals[8];
    int sum = 0;
#pragma unroll
    for (int j = 0; j < 8; ++j) {
        int i = t * 8 + j;
        vals[j] = (i < n) ? g_total[i] : 0;
        sum += vals[j];
    }
    sdata[t] = sum;
    __syncthreads();
    for (int off = 1; off < 1024; off <<= 1) {
        int v = (t >= off) ? sdata[t - off] : 0;
        __syncthreads();
        sdata[t] += v;
        __syncthreads();
    }
    int run = sdata[t] - sum;
#pragma unroll
    for (int j = 0; j < 8; ++j) {
        int i = t * 8 + j;
        if (i < n) g_rowStart[i] = run;
        run += vals[j];
    }
}

// ---------------- OF: warp-per-row exclusive scan (coalesced) ----------------
__global__ void offsets_kernel() {
    int wid  = threadIdx.x >> 5;
    int lane = threadIdx.x & 31;
    int r = blockIdx.x * (blockDim.x >> 5) + wid;
    if (r >= N_MAX) return;

    int4* p = reinterpret_cast<int4*>(&g_cnt[r * NCTA + lane * 8]);
    int4 a = p[0], bb = p[1];
    int v[8] = {a.x, a.y, a.z, a.w, bb.x, bb.y, bb.z, bb.w};
    int sum8 = v[0] + v[1] + v[2] + v[3] + v[4] + v[5] + v[6] + v[7];

    int s = sum8;
#pragma unroll
    for (int off = 1; off < 32; off <<= 1) {
        int u = __shfl_up_sync(0xffffffffu, s, off);
        if (lane >= off) s += u;
    }
    int run = g_rowStart[r] + (s - sum8);        // exclusive prefix

    int4 oa, ob;
    oa.x = run; run += v[0];
    oa.y = run; run += v[1];
    oa.z = run; run += v[2];
    oa.w = run; run += v[3];
    ob.x = run; run += v[4];
    ob.y = run; run += v[5];
    ob.z = run; run += v[6];
    ob.w = run;
    p[0] = oa; p[1] = ob;
}

// ---------------- B2: place pairs via smem cursors ----------------
__global__ void bin2_kernel(const int* __restrict__ src,
                            const int* __restrict__ dst,
                            const int* __restrict__ plen,
                            int n_pairs, int chunk) {
    __shared__ int cur[N_MAX];
    int t = threadIdx.x, nt = blockDim.x, c = blockIdx.x;
    for (int i = t; i < N_MAX; i += nt) cur[i] = g_cnt[i * NCTA + c];  // L2-hit
    __syncthreads();

    int begin = c * chunk;
    int end = min(begin + chunk, n_pairs);
    int nfull = begin + ((end - begin) & ~3);

    for (int base = begin + t * 4; base < nfull; base += nt * 4) {
        int4 s = *reinterpret_cast<const int4*>(src + base);
        int4 d = *reinterpret_cast<const int4*>(dst + base);
        int4 p = *reinterpret_cast<const int4*>(plen + base);
        int ss[4] = {s.x, s.y, s.z, s.w};
        int dd[4] = {d.x, d.y, d.z, d.w};
        int pp[4] = {p.x, p.y, p.z, p.w};
#pragma unroll
        for (int j = 0; j < 4; ++j) {
            int idx = min(pp[j], MAX_PATH_DISTANCE) - 1;     // 0..4
            int key = ((base + j + 1) << 3) | idx;           // >0, monotone in i
            int slot = atomicAdd(&cur[ss[j]], 1);
            g_bins[slot] = make_int2(key, dd[j]);
        }
    }
    for (int k = nfull + t; k < end; k += nt) {
        int idx = min(plen[k], MAX_PATH_DISTANCE) - 1;
        int key = ((k + 1) << 3) | idx;
        int slot = atomicAdd(&cur[src[k]], 1);
        g_bins[slot] = make_int2(key, dst[k]);
    }
}

// ---------------- AP: per-row resolve + dense write ----------------
__global__ void apply_kernel(float* __restrict__ out,
                             const float* __restrict__ b,
                             int n_nodes) {
    __shared__ int row[N_MAX];
    __shared__ float bs[8];

    int r = blockIdx.x;
    int t = threadIdx.x;
    int nt = blockDim.x;

    int n4 = n_nodes >> 2;
    int4 z4 = make_int4(0, 0, 0, 0);
    for (int i = t; i < n4; i += nt)
        reinterpret_cast<int4*>(row)[i] = z4;
    if (t < 8) bs[t] = b[min(t, MAX_PATH_DISTANCE - 1)];
    __syncthreads();

    int begin = g_rowStart[r];
    int end   = begin + g_total[r];

    for (int i = begin + t; i < end; i += nt) {
        int2 e = g_bins[i];                      // coalesced segment read
        atomicMax(&row[e.y], e.x);               // spread smem atomics
    }
    __syncthreads();

    float* orow = out + (size_t)r * n_nodes;
    for (int i = t; i < n4; i += nt) {
        int4 v = reinterpret_cast<const int4*>(row)[i];
        float4 o;
        o.x = v.x ? bs[v.x & 7] : 0.0f;
        o.y = v.y ? bs[v.y & 7] : 0.0f;
        o.z = v.z ? bs[v.z & 7] : 0.0f;
        o.w = v.w ? bs[v.w & 7] : 0.0f;
        reinterpret_cast<float4*>(orow)[i] = o;
    }
}

extern "C" void kernel_launch(void* const* d_in, const int* in_sizes, int n_in,
                              void* d_out, int out_size) {
    const int* src  = (const int*)d_in[1];
    const int* dst  = (const int*)d_in[2];
    const int* plen = (const int*)d_in[3];
    const float* b  = (const float*)d_in[4];

    int n_pairs = in_sizes[1];
    int n_nodes = (int)llround(sqrt((double)out_size));
    float* out = (float*)d_out;

    int chunk = (n_pairs + NCTA - 1) / NCTA;
    chunk = (chunk + 3) & ~3;                    // 4-aligned chunks for int4

    hist2_kernel<<<NCTA, 256>>>(src, n_pairs, chunk);
    rowtotal_kernel<<<N_MAX / 8, 256>>>();
    scan_kernel<<<1, 1024>>>(n_nodes);
    offsets_kernel<<<N_MAX / 8, 256>>>();
    bin2_kernel<<<NCTA, 256>>>(src, dst, plen, n_pairs, chunk);
    apply_kernel<<<n_nodes, 256>>>(out, b, n_nodes);
}